// round 15
// baseline (speedup 1.0000x reference)
#include <cuda_runtime.h>
#include <stdint.h>

#define NB 32
#define HH 512
#define WW 512
#define WPR 16     // 512 bits = 16 uint32 words per row
#define OWNR 14    // rows owned per k2 warp item
#define NI 37      // items per (batch, dir): ceil(512/14); 37*14=518 covers 512
#define NITEM (NB * 2 * NI)   // 2368
#define K2BLK (NITEM / 8)     // 296 blocks

__device__ uint32_t g_pmask[NB][HH][WPR];
__device__ uint32_t g_gmask[NB][HH][WPR];
// k1 per-block partials (16 blocks/batch):
// 0 Sp, 1 Spg, 2 pec, 3 pmc, 4 pjc, 5 gec, 6 gmc, 7 gjc, 8 Ie, 9 Im, 10 Ij,
// 11 N_p, 12 N_g
__device__ float g_part[NB][16][13];
// k2 medial per item
__device__ unsigned g_med[NB][2][NI];
__device__ unsigned g_ticket = 0;

struct Raw { float4 c; float l, r; };

__device__ __forceinline__ Raw load_raw(const float* __restrict__ img, size_t base,
                                        int r, int x0, int lane) {
    Raw o;
    if ((unsigned)r < HH) {
        const float* rp = img + base + (size_t)r * WW;
        o.c = __ldg((const float4*)rp + (x0 >> 2));
        o.l = 0.f; o.r = 0.f;
        if (lane == 0 && x0 > 0) o.l = __ldg(rp + x0 - 1);
        if (lane == 31 && x0 + 4 < WW) o.r = __ldg(rp + x0 + 4);
    } else {
        o.c = make_float4(0.f, 0.f, 0.f, 0.f);
        o.l = 0.f; o.r = 0.f;
    }
    return o;
}

__device__ __forceinline__ float4 make_h(const Raw& a, int lane) {
    float left  = __shfl_up_sync(0xFFFFFFFFu, a.c.w, 1);
    float right = __shfl_down_sync(0xFFFFFFFFu, a.c.x, 1);
    if (lane == 0)  left = a.l;
    if (lane == 31) right = a.r;
    float4 h;
    h.x = left  + a.c.x + a.c.y;
    h.y = a.c.x + a.c.y + a.c.z;
    h.z = a.c.y + a.c.z + a.c.w;
    h.w = a.c.z + a.c.w + right;
    return h;
}

// 6-bit gt window: bit p corresponds to column (x0-1+p); px j center = bit j+1.
__device__ __forceinline__ unsigned make_ext(const Raw& g, int lane) {
    unsigned nib = ((g.c.x > 0.5f) ? 2u : 0u) | ((g.c.y > 0.5f) ? 4u : 0u)
                 | ((g.c.z > 0.5f) ? 8u : 0u) | ((g.c.w > 0.5f) ? 16u : 0u);
    unsigned lb = __shfl_up_sync(0xFFFFFFFFu, nib, 1);
    unsigned rb = __shfl_down_sync(0xFFFFFFFFu, nib, 1);
    unsigned left  = (lane == 0)  ? ((g.l > 0.5f) ? 1u : 0u) : ((lb >> 4) & 1u);
    unsigned right = (lane == 31) ? ((g.r > 0.5f) ? 1u : 0u) : ((rb >> 1) & 1u);
    return nib | left | (right << 5);
}

// 512 blocks = (batch, x-strip 0..3, row-chunk 0..3), 256 thr = 8 warps;
// warp owns 16 rows x 128 cols. Pred: float stencil. Gt: bit stencil (exact).
__global__ void __launch_bounds__(256) k1_pixel(const float* __restrict__ pred,
                                                const float* __restrict__ gt) {
    const int tid = threadIdx.x, lane = tid & 31, w8 = tid >> 5;
    const int blk = blockIdx.x;
    const int b = blk >> 4, s = (blk >> 2) & 3, c = blk & 3;
    const int x0 = s * 128 + lane * 4;
    const int r0 = c * 128 + w8 * 16;
    const size_t base = (size_t)b * (HH * WW);

    Raw prm = load_raw(pred, base, r0 - 1, x0, lane);
    Raw grm = load_raw(gt,   base, r0 - 1, x0, lane);
    Raw pr0 = load_raw(pred, base, r0,     x0, lane);
    Raw gr0 = load_raw(gt,   base, r0,     x0, lane);
    Raw prn = load_raw(pred, base, r0 + 1, x0, lane);
    Raw grn = load_raw(gt,   base, r0 + 1, x0, lane);

    float4 php = make_h(prm, lane), phc = make_h(pr0, lane);
    float4 pcc = pr0.c;
    unsigned extp = make_ext(grm, lane), extc = make_ext(gr0, lane);

    float Sp = 0.f, Spg = 0.f;
    unsigned pec = 0, pmc = 0, pjc = 0, gec = 0, gmc = 0, gjc = 0;
    unsigned Ie = 0, Im = 0, Ij = 0, cP = 0, cG = 0;

    for (int i = 0; i < 16; i++) {
        const int r = r0 + i;
        Raw pr2 = load_raw(pred, base, r + 2, x0, lane);
        Raw gr2 = load_raw(gt,   base, r + 2, x0, lane);
        float4 phn = make_h(prn, lane);
        unsigned extn = make_ext(grn, lane);

        const float pcv[4] = {pcc.x, pcc.y, pcc.z, pcc.w};
        const float nps[4] = {php.x + phc.x + phn.x, php.y + phc.y + phn.y,
                              php.z + phc.z + phn.z, php.w + phc.w + phn.w};

        unsigned pn = 0;
#pragma unroll
        for (int j = 0; j < 4; j++) {
            const float pc = pcv[j];
            const bool pon = pc > 0.5f;
            const float np = nps[j] - pc;
            const unsigned pe = (pon && np == 1.0f) ? 1u : 0u;
            const unsigned pm = (pon && np == 2.0f) ? 1u : 0u;
            const unsigned pj = (pon && np > 2.0f) ? 1u : 0u;
            const unsigned gon = (extc >> (j + 1)) & 1u;
            const unsigned ng = __popc((extp >> j) & 7u)
                              + ((extc >> j) & 1u) + ((extc >> (j + 2)) & 1u)
                              + __popc((extn >> j) & 7u);
            const unsigned ge = gon & (unsigned)(ng == 1u);
            const unsigned gm = gon & (unsigned)(ng == 2u);
            const unsigned gj = gon & (unsigned)(ng > 2u);
            Sp += pc;
            Spg += gon ? pc : 0.f;
            pec += pe; pmc += pm; pjc += pj;
            gec += ge; gmc += gm; gjc += gj;
            Ie += pe & ge; Im += pm & gm; Ij += pj & gj;
            pn |= (unsigned)pon << j;
        }
        const unsigned gn = (extc >> 1) & 0xFu;
        cP += __popc(pn);
        cG += __popc(gn);

        // pack 8 lanes' nibbles into one 32-bit mask word
        const unsigned grpmask = 0xFFu << (lane & 24);
        const unsigned sh = (lane & 7) * 4;
        unsigned pw = __reduce_or_sync(grpmask, pn << sh);
        unsigned gw = __reduce_or_sync(grpmask, gn << sh);
        if ((lane & 7) == 0) {
            const int wi = s * 4 + (lane >> 3);
            g_pmask[b][r][wi] = pw;
            g_gmask[b][r][wi] = gw;
        }

        php = phc; phc = phn; pcc = prn.c; prn = pr2;
        extp = extc; extc = extn; grn = gr2;
    }

    // block reduce 13 values -> unique g_part slot
    float v13[13] = {Sp, Spg, (float)pec, (float)pmc, (float)pjc,
                     (float)gec, (float)gmc, (float)gjc,
                     (float)Ie, (float)Im, (float)Ij, (float)cP, (float)cG};
    __shared__ float sm_red[8][13];
#pragma unroll
    for (int k = 0; k < 13; k++) {
        float v = v13[k];
#pragma unroll
        for (int off = 16; off > 0; off >>= 1)
            v += __shfl_down_sync(0xFFFFFFFFu, v, off);
        if (lane == 0) sm_red[w8][k] = v;
    }
    __syncthreads();
    if (w8 == 0) {
#pragma unroll
        for (int k = 0; k < 13; k++) {
            float v = (lane < 8) ? sm_red[lane][k] : 0.0f;
#pragma unroll
            for (int off = 4; off > 0; off >>= 1)
                v += __shfl_down_sync(0xFFFFFFFFu, v, off);
            if (lane == 0) g_part[b][s * 4 + c][k] = v;
        }
    }
}

__device__ __forceinline__ unsigned warp_red(unsigned v) {
#pragma unroll
    for (int off = 16; off > 0; off >>= 1)
        v += __shfl_down_sync(0xFFFFFFFFu, v, off);
    return v;
}

__device__ __forceinline__ void load_row8(const uint4* p, int r, bool ok, uint64_t* R) {
#pragma unroll
    for (int q = 0; q < 4; q++) {
        uint4 a = ok ? __ldg(p + r * 4 + q) : make_uint4(0, 0, 0, 0);
        R[q * 2 + 0] = (uint64_t)a.x | ((uint64_t)a.y << 32);
        R[q * 2 + 1] = (uint64_t)a.z | ((uint64_t)a.w << 32);
    }
}

// 296 blocks, 8 warps; ONE item per warp = (batch, dir, 14-row span).
// TRANSPOSED: lane = row (14 owned + 2*9 halo = 32 lanes), 8 uint64/lane.
// Horizontal dilation = register funnels; vertical = 8 independent shuffle
// pairs per iteration. Early exit exact. Last block folds everything.
__global__ void __launch_bounds__(256) k2_dilate(float* __restrict__ out) {
    const int tid = threadIdx.x, lane = tid & 31, wid = tid >> 5;
    const int it = blockIdx.x * 8 + wid;
    const int b = it / (2 * NI);
    const int rem = it % (2 * NI);
    const int dir = rem / NI;
    const int Wc = rem % NI;
    const int own0 = Wc * OWNR;
    const int ownend = (own0 + OWNR > HH) ? HH : own0 + OWNR;
    const int r = own0 - 9 + lane;
    const bool in = (unsigned)r < HH;
    const bool owned = (r >= own0) && (r < ownend);

    const uint4* refp = (dir == 0) ? (const uint4*)&g_gmask[b][0][0]
                                   : (const uint4*)&g_pmask[b][0][0];
    const uint4* tgp  = (dir == 0) ? (const uint4*)&g_pmask[b][0][0]
                                   : (const uint4*)&g_gmask[b][0][0];

    uint64_t R[8], tg[8];
    load_row8(refp, in ? r : 0, in, R);
    load_row8(tgp, owned ? r : 0, owned, tg);

    unsigned acc = 0;
#pragma unroll 1
    for (int k = 1; k <= 9; k++) {
        uint64_t hz[8];
#pragma unroll
        for (int j = 0; j < 8; j++)
            hz[j] = R[j] | (R[j] << 1) | (R[j] >> 1)
                  | (j > 0 ? R[j - 1] >> 63 : 0ull)
                  | (j < 7 ? R[j + 1] << 63 : 0ull);
        uint64_t un = 0;
#pragma unroll
        for (int j = 0; j < 8; j++) {
            uint64_t u = __shfl_up_sync(0xFFFFFFFFu, hz[j], 1);
            uint64_t d = __shfl_down_sync(0xFFFFFFFFu, hz[j], 1);
            if (lane == 0)  u = 0ull;
            if (lane == 31) d = 0ull;
            uint64_t v = hz[j] | u | d;
            R[j] = v;
            uint64_t uc = tg[j] & ~v;   // tg==0 on unowned lanes
            un |= uc;
            acc += (unsigned)__popcll(uc);
        }
        if (!__any_sync(0xFFFFFFFFu, un != 0ull)) break;
    }
    {
        unsigned v = warp_red(acc);
        if (lane == 0) g_med[b][dir][Wc] = v;
    }

    // ---- ticket: last block computes the final scalar ----
    __shared__ bool isLast;
    __threadfence();
    __syncthreads();
    if (tid == 0) {
        unsigned old = atomicAdd(&g_ticket, 1u);
        isLast = (old == (unsigned)(gridDim.x - 1));
        if (isLast) __threadfence();
    }
    __syncthreads();
    if (!isLast) return;

    __shared__ float smf[32][8][15];
    {
        const int fb = tid >> 3, grp = tid & 7;
        float part[15];
#pragma unroll
        for (int k = 0; k < 15; k++) part[k] = 0.f;
#pragma unroll
        for (int q = 0; q < 2; q++) {
            int sc = grp * 2 + q;
#pragma unroll
            for (int k = 0; k < 13; k++) part[k] += g_part[fb][sc][k];
        }
#pragma unroll
        for (int q = 0; q < 5; q++) {
            int Wq = grp * 5 + q;
            if (Wq < NI) {
                part[13] += (float)g_med[fb][0][Wq];
                part[14] += (float)g_med[fb][1][Wq];
            }
        }
#pragma unroll
        for (int k = 0; k < 15; k++) smf[fb][grp][k] = part[k];
    }
    __syncthreads();
    if (tid < 32) {
        const int bb = tid;
        float a[15];
#pragma unroll
        for (int k = 0; k < 15; k++) {
            float v = 0.f;
#pragma unroll
            for (int g2 = 0; g2 < 8; g2++) v += smf[bb][g2][k];
            a[k] = v;
        }
        const float Sp = a[0], Spg = a[1];
        const float pec = a[2], pmc = a[3], pjc = a[4];
        const float gec = a[5], gmc = a[6], gjc = a[7];
        const float Ie = a[8], Im = a[9], Ij = a[10];
        const float Np = a[11], Ng = a[12];
        const float medP = a[13] + Np;   // + d>=1 term for every on-pixel
        const float medG = a[14] + Ng;
        const float Sg = Ng;

        float dice = (2.0f * Spg + 1.0f) / (Sp + Sg + 1.0f);
        float eiou = (Ie + 1.0f) / (pec + gec - Ie + 1.0f);
        float miou = (Im + 1.0f) / (pmc + gmc - Im + 1.0f);
        float jiou = (Ij + 1.0f) / (pjc + gjc - Ij + 1.0f);
        float total3 = gec + gjc + gmc + 1.0f;
        float sloss = 1.0f - ((gec / total3) * eiou + (gjc / total3) * jiou
                              + (gmc / total3) * miou);
        float p2g = medP / (Np + 1.0f);
        float g2p = medG / (Ng + 1.0f);
        float med = ((p2g + g2p) * 0.5f) / 10.0f;

        float sd = dice, ss = sloss, sme = med;
#pragma unroll
        for (int off = 16; off > 0; off >>= 1) {
            sd  += __shfl_down_sync(0xFFFFFFFFu, sd, off);
            ss  += __shfl_down_sync(0xFFFFFFFFu, ss, off);
            sme += __shfl_down_sync(0xFFFFFFFFu, sme, off);
        }
        if (tid == 0) {
            float dice_loss = 1.0f - sd / 32.0f;
            float structural_loss = ss / 32.0f;
            float medial_loss = sme / 32.0f;
            float avg = (dice_loss + structural_loss + medial_loss) / 3.0f;
            out[0] = dice_loss / (dice_loss + 1.0f) * avg
                   + structural_loss / (structural_loss + 1.0f) * avg
                   + medial_loss / (medial_loss + 1.0f) * avg;
            g_ticket = 0u;  // reset for next graph replay
        }
    }
}

extern "C" void kernel_launch(void* const* d_in, const int* in_sizes, int n_in,
                              void* d_out, int out_size) {
    const float* pred = (const float*)d_in[0];
    const float* gt   = (const float*)d_in[1];
    float* out = (float*)d_out;

    k1_pixel<<<NB * 16, 256>>>(pred, gt);   // 512 blocks: (batch, strip, chunk)
    k2_dilate<<<K2BLK, 256>>>(out);         // 296 blocks: one warp item per warp
}

// round 16
// speedup vs baseline: 1.0805x; 1.0805x over previous
#include <cuda_runtime.h>
#include <stdint.h>

#define NB 32
#define HH 512
#define WW 512
#define WPR 16   // 512 bits = 16 uint32 words per row
#define OWN 22   // rows owned per k2 warp item
#define RPL 10   // rows per lane slot (4 slots * 10 = 40 = 22 + 2*9 halo)
#define NW 24    // warp items per (batch, dir)

// Single accumulator, fed by atomicAdd from k1 and k2:
// 0 Sp, 1 Spg, 2 pec, 3 pmc, 4 pjc, 5 gec, 6 gmc, 7 gjc, 8 Ie, 9 Im, 10 Ij,
// 11 med_p2g, 12 med_g2p, 13 N_p, 14 N_g
__device__ float g_acc[NB][16];   // zero-init; finale resets after each replay
__device__ uint32_t g_pmask[NB][HH][WPR];
__device__ uint32_t g_gmask[NB][HH][WPR];
__device__ uint32_t g_pe[NB][HH][WPR];
__device__ uint32_t g_pm[NB][HH][WPR];
__device__ uint32_t g_pj[NB][HH][WPR];
__device__ unsigned g_ticket = 0;

struct Raw { float4 c; float l, r; };

__device__ __forceinline__ Raw load_raw(const float* __restrict__ img, size_t base,
                                        int r, int x0, int lane) {
    Raw o;
    if ((unsigned)r < HH) {
        const float* rp = img + base + (size_t)r * WW;
        o.c = __ldg((const float4*)rp + (x0 >> 2));
        o.l = 0.f; o.r = 0.f;
        if (lane == 0 && x0 > 0) o.l = __ldg(rp + x0 - 1);
        if (lane == 31 && x0 + 4 < WW) o.r = __ldg(rp + x0 + 4);
    } else {
        o.c = make_float4(0.f, 0.f, 0.f, 0.f);
        o.l = 0.f; o.r = 0.f;
    }
    return o;
}

__device__ __forceinline__ float4 make_h(const Raw& a, int lane) {
    float left  = __shfl_up_sync(0xFFFFFFFFu, a.c.w, 1);
    float right = __shfl_down_sync(0xFFFFFFFFu, a.c.x, 1);
    if (lane == 0)  left = a.l;
    if (lane == 31) right = a.r;
    float4 h;
    h.x = left  + a.c.x + a.c.y;
    h.y = a.c.x + a.c.y + a.c.z;
    h.z = a.c.y + a.c.z + a.c.w;
    h.w = a.c.z + a.c.w + right;
    return h;
}

// 512 blocks = (batch, x-strip, row-chunk), 256 threads, warp owns 16 rows.
// Pred float stencil + mask packing; gt structural classes deferred to k2.
__global__ void __launch_bounds__(256) k1_pixel(const float* __restrict__ pred,
                                                const float* __restrict__ gt) {
    const int tid = threadIdx.x, lane = tid & 31, w8 = tid >> 5;
    const int blk = blockIdx.x;
    const int b = blk >> 4, s = (blk >> 2) & 3, c = blk & 3;
    const int x0 = s * 128 + lane * 4;
    const int r0 = c * 128 + w8 * 16;
    const size_t base = (size_t)b * (HH * WW);

    Raw prm = load_raw(pred, base, r0 - 1, x0, lane);
    Raw pr0 = load_raw(pred, base, r0,     x0, lane);
    Raw prn = load_raw(pred, base, r0 + 1, x0, lane);
    float4 php = make_h(prm, lane), phc = make_h(pr0, lane);
    float4 pcc = pr0.c;
    float4 gcur = __ldg((const float4*)(gt + base + (size_t)r0 * WW + x0));

    float Sp = 0.f, Spg = 0.f;
    unsigned pec = 0, pmc = 0, pjc = 0, cP = 0, cG = 0;

#pragma unroll 2
    for (int i = 0; i < 16; i++) {
        const int r = r0 + i;
        Raw pr2 = load_raw(pred, base, r + 2, x0, lane);
        float4 gnx = make_float4(0.f, 0.f, 0.f, 0.f);
        if (r + 1 < HH)
            gnx = __ldg((const float4*)(gt + base + (size_t)(r + 1) * WW + x0));
        float4 phn = make_h(prn, lane);

        const float pcv[4] = {pcc.x, pcc.y, pcc.z, pcc.w};
        const float gcv[4] = {gcur.x, gcur.y, gcur.z, gcur.w};
        const float nps[4] = {php.x + phc.x + phn.x, php.y + phc.y + phn.y,
                              php.z + phc.z + phn.z, php.w + phc.w + phn.w};

        unsigned pn = 0, gn = 0, pen = 0, pmn = 0, pjn = 0;
#pragma unroll
        for (int j = 0; j < 4; j++) {
            const float pc = pcv[j], gc = gcv[j];
            const bool pon = pc > 0.5f;
            const bool gon = gc > 0.5f;
            const float np = nps[j] - pc;
            const bool pe = pon && (np == 1.0f);
            const bool pm = pon && (np == 2.0f);
            const bool pj = pon && (np > 2.0f);
            Sp += pc;
            Spg += gon ? pc : 0.f;
            pn |= (unsigned)pon << j;
            gn |= (unsigned)gon << j;
            pen |= (unsigned)pe << j;
            pmn |= (unsigned)pm << j;
            pjn |= (unsigned)pj << j;
        }
        cP += __popc(pn); cG += __popc(gn);
        pec += __popc(pen); pmc += __popc(pmn); pjc += __popc(pjn);

        const unsigned grpmask = 0xFFu << (lane & 24);
        const unsigned sh = (lane & 7) * 4;
        unsigned pw = __reduce_or_sync(grpmask, pn << sh);
        unsigned gw = __reduce_or_sync(grpmask, gn << sh);
        unsigned ew = __reduce_or_sync(grpmask, pen << sh);
        unsigned mw = __reduce_or_sync(grpmask, pmn << sh);
        unsigned jw = __reduce_or_sync(grpmask, pjn << sh);
        if ((lane & 7) == 0) {
            const int wi = s * 4 + (lane >> 3);
            g_pmask[b][r][wi] = pw;
            g_gmask[b][r][wi] = gw;
            g_pe[b][r][wi] = ew;
            g_pm[b][r][wi] = mw;
            g_pj[b][r][wi] = jw;
        }

        php = phc; phc = phn; pcc = prn.c; prn = pr2; gcur = gnx;
    }

    // warp reduce 13 values, block reduce, then atomics to g_acc
    float v13[13] = {Sp, Spg, (float)pec, (float)pmc, (float)pjc,
                     0.f, 0.f, 0.f, 0.f, 0.f, 0.f, (float)cP, (float)cG};
    __shared__ float sm_red[8][13];
#pragma unroll
    for (int k = 0; k < 13; k++) {
        float v = v13[k];
#pragma unroll
        for (int off = 16; off > 0; off >>= 1)
            v += __shfl_down_sync(0xFFFFFFFFu, v, off);
        if (lane == 0) sm_red[w8][k] = v;
    }
    __syncthreads();
    if (w8 == 0) {
#pragma unroll
        for (int k = 0; k < 13; k++) {
            float v = (lane < 8) ? sm_red[lane][k] : 0.0f;
#pragma unroll
            for (int off = 4; off > 0; off >>= 1)
                v += __shfl_down_sync(0xFFFFFFFFu, v, off);
            if (lane == 0 && v != 0.0f) {
                // slots: 0..4 direct; 11 -> 13 (N_p), 12 -> 14 (N_g)
                int slot = (k < 11) ? k : (k + 2);
                atomicAdd(&g_acc[b][slot], v);
            }
        }
    }
}

__device__ __forceinline__ uint64_t shfl64_up8(uint64_t v) {
    unsigned lo = __shfl_up_sync(0xFFFFFFFFu, (unsigned)v, 8);
    unsigned hi = __shfl_up_sync(0xFFFFFFFFu, (unsigned)(v >> 32), 8);
    return ((uint64_t)hi << 32) | lo;
}
__device__ __forceinline__ uint64_t shfl64_dn8(uint64_t v) {
    unsigned lo = __shfl_down_sync(0xFFFFFFFFu, (unsigned)v, 8);
    unsigned hi = __shfl_down_sync(0xFFFFFFFFu, (unsigned)(v >> 32), 8);
    return ((uint64_t)hi << 32) | lo;
}
__device__ __forceinline__ unsigned warp_red(unsigned v) {
#pragma unroll
    for (int off = 16; off > 0; off >>= 1)
        v += __shfl_down_sync(0xFFFFFFFFu, v, off);
    return v;
}

// 192 blocks = (batch, dir, third). 8 warps; warp owns 22 rows (+9 halos)
// in registers (lane = word x slot layout). dir=0 also computes gt
// structural classes via bit CSA + intersections with PE/PM/PJ masks.
// All partials go to g_acc via atomicAdd; ticket-last block finalizes.
__global__ void __launch_bounds__(256) k2_dilate(float* __restrict__ out) {
    const int tid = threadIdx.x, lane = tid & 31, wid = tid >> 5;
    const int blk = blockIdx.x;
    const int b = blk / 6;
    const int rem = blk % 6;
    const int dir = rem / 3;
    const int W = (rem % 3) * 8 + wid;
    const int ownstart = W * OWN;
    const int ownend = (ownstart + OWN > HH) ? HH : ownstart + OWN;
    const int loadstart = ownstart - 9;
    const int w = lane & 7, s = lane >> 3;

    const uint64_t* refm = (dir == 0) ? (const uint64_t*)&g_gmask[b][0][0]
                                      : (const uint64_t*)&g_pmask[b][0][0];
    const uint64_t* tgm  = (dir == 0) ? (const uint64_t*)&g_pmask[b][0][0]
                                      : (const uint64_t*)&g_gmask[b][0][0];

    uint64_t cur[RPL], tg[RPL];
#pragma unroll
    for (int j = 0; j < RPL; j++) {
        int rr = loadstart + s * RPL + j;
        bool in = (unsigned)rr < HH;
        cur[j] = in ? refm[rr * 8 + w] : 0ull;
        bool ow = (rr >= ownstart) && (rr < ownend);
        tg[j] = ow ? tgm[rr * 8 + w] : 0ull;
    }

    // ---- structural on gt (dir == 0, block-uniform branch) ----
    if (dir == 0) {
        uint64_t cu_m1 = shfl64_up8(cur[RPL - 1]);
        uint64_t cu_p1 = shfl64_dn8(cur[0]);
        if (s == 0) cu_m1 = 0ull;
        if (s == 3) cu_p1 = 0ull;
        unsigned gec = 0, gmc = 0, gjc = 0, Ie = 0, Im = 0, Ij = 0;
#pragma unroll
        for (int j = 0; j < RPL; j++) {
            uint64_t ra = (j > 0) ? cur[j - 1] : cu_m1;
            uint64_t rb = cur[j];
            uint64_t rc = (j < RPL - 1) ? cur[j + 1] : cu_p1;
            uint64_t rows[3] = {ra, rb, rc};
            uint64_t fl[3], fr[3];
#pragma unroll
            for (int t = 0; t < 3; t++) {
                unsigned hb = (unsigned)(rows[t] >> 63);
                unsigned lb = (unsigned)rows[t] & 1u;
                unsigned vfl = __shfl_up_sync(0xFFFFFFFFu, hb, 1);
                unsigned vfr = __shfl_down_sync(0xFFFFFFFFu, lb, 1);
                fl[t] = (rows[t] << 1) | (w > 0 ? (uint64_t)vfl : 0ull);
                fr[t] = (rows[t] >> 1) | (w < 7 ? ((uint64_t)vfr) << 63 : 0ull);
            }
            int rr = loadstart + s * RPL + j;
            if (rr >= ownstart && rr < ownend) {
                uint64_t in8[8] = {fl[0], ra, fr[0], fl[1], fr[1], fl[2], rc, fr[2]};
                uint64_t c0 = 0, c1 = 0, ge4 = 0;
#pragma unroll
                for (int t = 0; t < 8; t++) {
                    uint64_t car = c0 & in8[t];
                    c0 ^= in8[t];
                    uint64_t car2 = c1 & car;
                    c1 ^= car;
                    ge4 |= car2;
                }
                uint64_t g = rb;
                uint64_t geW = g & c0 & ~c1 & ~ge4;
                uint64_t gmW = g & ~c0 & c1 & ~ge4;
                uint64_t gjW = g & (ge4 | (c0 & c1));
                gec += __popcll(geW); gmc += __popcll(gmW); gjc += __popcll(gjW);
                uint64_t peW = ((const uint64_t*)&g_pe[b][0][0])[rr * 8 + w];
                uint64_t pmW = ((const uint64_t*)&g_pm[b][0][0])[rr * 8 + w];
                uint64_t pjW = ((const uint64_t*)&g_pj[b][0][0])[rr * 8 + w];
                Ie += __popcll(geW & peW);
                Im += __popcll(gmW & pmW);
                Ij += __popcll(gjW & pjW);
            }
        }
        unsigned sr[6] = {gec, gmc, gjc, Ie, Im, Ij};
#pragma unroll
        for (int t = 0; t < 6; t++) {
            unsigned v = warp_red(sr[t]);
            if (lane == 0 && v != 0u) atomicAdd(&g_acc[b][5 + t], (float)v);
        }
    }

    // ---- iterated dilation with early exit ----
    unsigned acc = 0;
    uint64_t hz[RPL];
#pragma unroll 1
    for (int k = 1; k <= 9; k++) {
#pragma unroll
        for (int j = 0; j < RPL; j++) {
            unsigned hb = (unsigned)(cur[j] >> 63);
            unsigned lb = (unsigned)cur[j] & 1u;
            unsigned vfl = __shfl_up_sync(0xFFFFFFFFu, hb, 1);
            unsigned vfr = __shfl_down_sync(0xFFFFFFFFu, lb, 1);
            hz[j] = cur[j] | (cur[j] << 1) | (cur[j] >> 1)
                  | (w > 0 ? (uint64_t)vfl : 0ull)
                  | (w < 7 ? ((uint64_t)vfr) << 63 : 0ull);
        }
        uint64_t hz_m1 = shfl64_up8(hz[RPL - 1]);
        uint64_t hz_p1 = shfl64_dn8(hz[0]);
        if (s == 0) hz_m1 = 0ull;
        if (s == 3) hz_p1 = 0ull;
        uint64_t un = 0;
#pragma unroll
        for (int j = 0; j < RPL; j++) {
            uint64_t v = hz[j] | ((j > 0) ? hz[j - 1] : hz_m1)
                               | ((j < RPL - 1) ? hz[j + 1] : hz_p1);
            cur[j] = v;
            uint64_t u = tg[j] & ~v;
            un |= u;
            acc += (unsigned)__popcll(u);
        }
        if (!__any_sync(0xFFFFFFFFu, un != 0ull)) break;
    }
    {
        unsigned v = warp_red(acc);
        if (lane == 0 && v != 0u) atomicAdd(&g_acc[b][11 + dir], (float)v);
    }

    // ---- ticket: last block computes the final scalar ----
    __shared__ bool isLast;
    __threadfence();
    __syncthreads();
    if (tid == 0) {
        unsigned old = atomicAdd(&g_ticket, 1u);
        isLast = (old == (unsigned)(gridDim.x - 1));
        if (isLast) __threadfence();
    }
    __syncthreads();
    if (!isLast) return;

    if (tid < 32) {
        const int bb = tid;
        float a[16];
#pragma unroll
        for (int k = 0; k < 16; k++) a[k] = g_acc[bb][k];
        const float Sp = a[0], Spg = a[1];
        const float pec = a[2], pmc = a[3], pjc = a[4];
        const float gec = a[5], gmc = a[6], gjc = a[7];
        const float Ie = a[8], Im = a[9], Ij = a[10];
        const float Np = a[13], Ng = a[14];
        const float medP = a[11] + Np;   // + d>=1 term for every on-pixel
        const float medG = a[12] + Ng;
        const float Sg = Ng;

        float dice = (2.0f * Spg + 1.0f) / (Sp + Sg + 1.0f);
        float eiou = (Ie + 1.0f) / (pec + gec - Ie + 1.0f);
        float miou = (Im + 1.0f) / (pmc + gmc - Im + 1.0f);
        float jiou = (Ij + 1.0f) / (pjc + gjc - Ij + 1.0f);
        float total3 = gec + gjc + gmc + 1.0f;
        float sloss = 1.0f - ((gec / total3) * eiou + (gjc / total3) * jiou
                              + (gmc / total3) * miou);
        float p2g = medP / (Np + 1.0f);
        float g2p = medG / (Ng + 1.0f);
        float med = ((p2g + g2p) * 0.5f) / 10.0f;

        float sd = dice, ss = sloss, sme = med;
#pragma unroll
        for (int off = 16; off > 0; off >>= 1) {
            sd  += __shfl_down_sync(0xFFFFFFFFu, sd, off);
            ss  += __shfl_down_sync(0xFFFFFFFFu, ss, off);
            sme += __shfl_down_sync(0xFFFFFFFFu, sme, off);
        }
        // reset accumulators for the next graph replay
#pragma unroll
        for (int k = 0; k < 16; k++) g_acc[bb][k] = 0.f;
        if (tid == 0) {
            float dice_loss = 1.0f - sd / 32.0f;
            float structural_loss = ss / 32.0f;
            float medial_loss = sme / 32.0f;
            float avg = (dice_loss + structural_loss + medial_loss) / 3.0f;
            out[0] = dice_loss / (dice_loss + 1.0f) * avg
                   + structural_loss / (structural_loss + 1.0f) * avg
                   + medial_loss / (medial_loss + 1.0f) * avg;
            g_ticket = 0u;
        }
    }
}

extern "C" void kernel_launch(void* const* d_in, const int* in_sizes, int n_in,
                              void* d_out, int out_size) {
    const float* pred = (const float*)d_in[0];
    const float* gt   = (const float*)d_in[1];
    float* out = (float*)d_out;

    k1_pixel<<<NB * 16, 256>>>(pred, gt);   // 512 blocks: (batch, strip, chunk)
    k2_dilate<<<NB * 6, 256>>>(out);        // 192 blocks: (batch, dir, third)
}